// round 1
// baseline (speedup 1.0000x reference)
#include <cuda_runtime.h>
#include <math.h>

#define Bb 2
#define Tt 512
#define Cc 256
#define Hh 8
#define Ee 32
#define NET 16
#define BT (Bb*Tt)      // 1024
#define C3 (3*Cc)       // 768

// ------- scratch (device globals: no allocation allowed) -------
__device__ float g_qkv[BT*C3];        // 3 MB
__device__ float g_q[Bb*Hh*Tt*Ee];    // 1 MB
__device__ float g_k[Bb*Hh*Tt*Ee];
__device__ float g_v[Bb*Hh*Tt*Ee];
__device__ int   g_bmT[Bb*Tt*Tt];     // 2 MB  bmT[b][i][j] = bm[b][j][i]
__device__ float g_ekt[Hh*NET*Ee];    // [h][t][e]
__device__ float g_evt[Hh*NET*Ee];
__device__ float g_y[BT*Cc];          // 1 MB (b,t,c) pre-proj

// ---------------- generic 64x64 fp32 GEMM (exact tiles) ----------------
__global__ void gemm_tiled(const float* __restrict__ A, const float* __restrict__ Bm,
                           float* __restrict__ Cm, int N, int K) {
    __shared__ float As[64][17];   // [m][k]
    __shared__ float Bs[16][68];   // [k][n]
    const int tid = threadIdx.x;
    const int tr = tid >> 4;       // 0..15
    const int tc = tid & 15;       // 0..15
    const int row0 = blockIdx.y * 64;
    const int col0 = blockIdx.x * 64;
    float acc[4][4] = {};
    for (int k0 = 0; k0 < K; k0 += 16) {
        #pragma unroll
        for (int x = tid; x < 1024; x += 256) {
            int r = x >> 4, c = x & 15;
            As[r][c] = A[(row0 + r) * K + k0 + c];
        }
        #pragma unroll
        for (int x = tid; x < 1024; x += 256) {
            int r = x >> 6, c = x & 63;
            Bs[r][c] = Bm[(k0 + r) * N + col0 + c];
        }
        __syncthreads();
        #pragma unroll
        for (int kk = 0; kk < 16; kk++) {
            float a[4], bv[4];
            #pragma unroll
            for (int u = 0; u < 4; u++) a[u] = As[tr * 4 + u][kk];
            #pragma unroll
            for (int v = 0; v < 4; v++) bv[v] = Bs[kk][tc * 4 + v];
            #pragma unroll
            for (int u = 0; u < 4; u++)
                #pragma unroll
                for (int v = 0; v < 4; v++) acc[u][v] += a[u] * bv[v];
        }
        __syncthreads();
    }
    #pragma unroll
    for (int u = 0; u < 4; u++)
        #pragma unroll
        for (int v = 0; v < 4; v++)
            Cm[(row0 + tr * 4 + u) * N + col0 + tc * 4 + v] = acc[u][v];
}

// ---------------- reshape qkv (bt, 3C) -> q/k/v (b,h,t,e) ----------------
__global__ void reshape_qkv() {
    int idx = blockIdx.x * blockDim.x + threadIdx.x;
    if (idx >= BT * C3) return;
    int bt = idx / C3;
    int col = idx % C3;
    int which = col >> 8;          // 0=q 1=k 2=v (C=256)
    int c0 = col & 255;
    int h = c0 >> 5, e = c0 & 31;
    int b = bt >> 9, t = bt & 511; // T=512
    float val = g_qkv[idx];
    int dst = (((b * Hh + h) * Tt) + t) * Ee + e;
    if (which == 0) g_q[dst] = val;
    else if (which == 1) g_k[dst] = val;
    else g_v[dst] = val;
}

// ---------------- edge-type tables: ekt/evt [h][t16][e] ----------------
__global__ void edge_tables(const float* __restrict__ eet,
                            const float* __restrict__ wek,
                            const float* __restrict__ wev) {
    int idx = blockIdx.x * blockDim.x + threadIdx.x;  // 0 .. NET*C
    if (idx >= NET * Cc) return;
    int t = idx / Cc, c0 = idx % Cc;
    int h = c0 >> 5, e = c0 & 31;
    float sk = 0.f, sv = 0.f;
    for (int c = 0; c < Cc; c++) {
        float a = eet[t * Cc + c];
        sk += a * wek[c * Cc + c0];
        sv += a * wev[c * Cc + c0];
    }
    g_ekt[(h * NET + t) * Ee + e] = sk;
    g_evt[(h * NET + t) * Ee + e] = sv;
}

// ---------------- transpose bias_matrix ----------------
__global__ void transpose_bm(const int* __restrict__ bm) {
    __shared__ int tile[32][33];
    int b = blockIdx.z;
    int i0 = blockIdx.y * 32, j0 = blockIdx.x * 32;
    tile[threadIdx.y][threadIdx.x] = bm[b * Tt * Tt + (i0 + threadIdx.y) * Tt + j0 + threadIdx.x];
    __syncthreads();
    g_bmT[b * Tt * Tt + (j0 + threadIdx.y) * Tt + i0 + threadIdx.x] = tile[threadIdx.x][threadIdx.y];
}

// ---------------- fused causal attention with edge modulation ----------------
// grid: (T/8, H, B), block 256 (8 warps). One warp per query row, lane = e = j.
__global__ void attn_kernel(const int* __restrict__ bm, const float* __restrict__ abt) {
    const int b = blockIdx.z, h = blockIdx.y;
    const int w = threadIdx.x >> 5, lane = threadIdx.x & 31;
    // heavy (high-i) tiles first for load balance under causal mask
    const int it = gridDim.x - 1 - blockIdx.x;
    const int i = it * 8 + w;

    __shared__ float k_s[32 * 33];
    __shared__ float v_s[32 * 33];
    __shared__ float qek[8 * NET * 33];   // per-warp modulated q: q[e]*ekt[t][e]
    __shared__ float evt_s[NET * 33];
    __shared__ float bias_s[NET];

    const float* qb = g_q + ((size_t)(b * Hh + h) * Tt) * Ee;
    const float* kb = g_k + ((size_t)(b * Hh + h) * Tt) * Ee;
    const float* vb = g_v + ((size_t)(b * Hh + h) * Tt) * Ee;

    // evt table + bias table for this head
    for (int x = threadIdx.x; x < NET * Ee; x += 256)
        evt_s[(x >> 5) * 33 + (x & 31)] = g_evt[h * NET * Ee + x];
    if (threadIdx.x < NET) bias_s[threadIdx.x] = abt[threadIdx.x * Hh + h];

    // per-warp qek precompute
    float qv = qb[i * Ee + lane];
    #pragma unroll
    for (int t = 0; t < NET; t++)
        qek[(w * NET + t) * 33 + lane] = qv * g_ekt[(h * NET + t) * Ee + lane];
    __syncthreads();

    float m = -INFINITY, l = 0.f, acc = 0.f;
    const float inv_scale = 0.1767766952966369f;   // 1/sqrt(32)
    const int ntiles = ((it * 8 + 7) >> 5) + 1;
    const int* bmT_row = g_bmT + b * Tt * Tt + i * Tt;
    const int* bm_row = bm + b * Tt * Tt + i * Tt;

    for (int tile = 0; tile < ntiles; tile++) {
        const int j0 = tile * 32;
        // cooperative k/v tile load (32 x 32 each)
        for (int x = threadIdx.x; x < 32 * Ee; x += 256) {
            int jj = x >> 5, e = x & 31;
            k_s[jj * 33 + e] = kb[(j0 + jj) * Ee + e];
            v_s[jj * 33 + e] = vb[(j0 + jj) * Ee + e];
        }
        __syncthreads();

        // ---- phase 1: lane = j. score s_j = sum_e qek[et_j][e] * k[j][e]
        const int jg = j0 + lane;
        const int et = bmT_row[jg];     // bm[b, j, i] — modulation type
        const int et2 = bm_row[jg];     // bm[b, i, j] — additive bias type
        float s = 0.f;
        const float* qrow = &qek[(w * NET + et) * 33];
        const float* krow = &k_s[lane * 33];
        #pragma unroll
        for (int e = 0; e < 32; e++) s += qrow[e] * krow[e];

        const bool valid = (jg <= i);
        float sv = valid ? s * inv_scale + bias_s[et2] : -INFINITY;

        // ---- online softmax (per-lane holds one j's score)
        float tmax = sv;
        #pragma unroll
        for (int o = 16; o; o >>= 1) tmax = fmaxf(tmax, __shfl_xor_sync(0xffffffffu, tmax, o));
        float m_new = fmaxf(m, tmax);
        float p = valid ? __expf(sv - m_new) : 0.f;
        float corr = __expf(m - m_new);
        float psum = p;
        #pragma unroll
        for (int o = 16; o; o >>= 1) psum += __shfl_xor_sync(0xffffffffu, psum, o);
        l = l * corr + psum;
        m = m_new;
        acc *= corr;

        // ---- phase 2: lane = e. acc[e] += p_j * v[j][e] * evt[et_j][e]
        #pragma unroll
        for (int jj = 0; jj < 32; jj++) {
            float pj = __shfl_sync(0xffffffffu, p, jj);
            int etj = __shfl_sync(0xffffffffu, et, jj);
            acc += pj * v_s[jj * 33 + lane] * evt_s[etj * 33 + lane];
        }
        __syncthreads();
    }
    g_y[(b * Tt + i) * Cc + h * Ee + lane] = acc / l;
}

// ---------------- launch ----------------
extern "C" void kernel_launch(void* const* d_in, const int* in_sizes, int n_in,
                              void* d_out, int out_size) {
    const float* x    = (const float*)d_in[0];
    const int*   bm   = (const int*)d_in[1];
    const float* w_attn = (const float*)d_in[2];
    const float* w_proj = (const float*)d_in[3];
    const float* w_ek = (const float*)d_in[4];
    const float* w_ev = (const float*)d_in[5];
    const float* eet  = (const float*)d_in[6];
    const float* abt  = (const float*)d_in[7];
    float* out = (float*)d_out;

    float* gqkv; cudaGetSymbolAddress((void**)&gqkv, g_qkv);
    float* gy;   cudaGetSymbolAddress((void**)&gy, g_y);

    // 1) qkv = x @ w_attn : (1024 x 768), K=256
    gemm_tiled<<<dim3(C3 / 64, BT / 64), 256>>>(x, w_attn, gqkv, C3, Cc);
    // 2) reshape to (B,H,T,E)
    reshape_qkv<<<(BT * C3 + 255) / 256, 256>>>();
    // 3) edge tables (16 x 256 each)
    edge_tables<<<(NET * Cc + 255) / 256, 256>>>(eet, w_ek, w_ev);
    // 4) transpose bias_matrix
    transpose_bm<<<dim3(Tt / 32, Tt / 32, Bb), dim3(32, 32)>>>(bm);
    // 5) fused attention -> g_y (b,t,c)
    attn_kernel<<<dim3(Tt / 8, Hh, Bb), 256>>>(bm, abt);
    // 6) out = y @ w_proj : (1024 x 256), K=256
    gemm_tiled<<<dim3(Cc / 64, BT / 64), 256>>>(gy, w_proj, out, Cc, Cc);
}

// round 2
// speedup vs baseline: 1.2996x; 1.2996x over previous
#include <cuda_runtime.h>
#include <math.h>

#define Bb 2
#define Tt 512
#define Cc 256
#define Hh 8
#define Ee 32
#define NET 16
#define BT (Bb*Tt)      // 1024
#define C3 (3*Cc)       // 768

// ------- scratch (device globals: no allocation allowed) -------
__device__ float g_q[Bb*Hh*Tt*Ee];    // 1 MB each, (b,h,t,e)
__device__ float g_k[Bb*Hh*Tt*Ee];
__device__ float g_v[Bb*Hh*Tt*Ee];
__device__ float g_ekt[Hh*NET*Ee];    // [h][type][e]
__device__ float g_evt[Hh*NET*Ee];
__device__ float g_y[BT*Cc];          // (b,t,c) pre-proj

// ---------------- 64x64 fp32 GEMM core (exact tiles) ----------------
// qkv variant: fused reshape epilogue -> g_q/g_k/g_v
__global__ void __launch_bounds__(256) gemm_qkv(const float* __restrict__ A,
                                                const float* __restrict__ Bm) {
    __shared__ float As[64][17];
    __shared__ float Bs[16][68];
    const int tid = threadIdx.x;
    const int tr = tid >> 4, tc = tid & 15;
    const int row0 = blockIdx.y * 64;
    const int col0 = blockIdx.x * 64;
    float acc[4][4] = {};
    for (int k0 = 0; k0 < Cc; k0 += 16) {
        #pragma unroll
        for (int x = tid; x < 1024; x += 256) {
            int r = x >> 4, c = x & 15;
            As[r][c] = A[(row0 + r) * Cc + k0 + c];
        }
        #pragma unroll
        for (int x = tid; x < 1024; x += 256) {
            int r = x >> 6, c = x & 63;
            Bs[r][c] = Bm[(k0 + r) * C3 + col0 + c];
        }
        __syncthreads();
        #pragma unroll
        for (int kk = 0; kk < 16; kk++) {
            float a[4], bv[4];
            #pragma unroll
            for (int u = 0; u < 4; u++) a[u] = As[tr * 4 + u][kk];
            #pragma unroll
            for (int v = 0; v < 4; v++) bv[v] = Bs[kk][tc * 4 + v];
            #pragma unroll
            for (int u = 0; u < 4; u++)
                #pragma unroll
                for (int v = 0; v < 4; v++) acc[u][v] += a[u] * bv[v];
        }
        __syncthreads();
    }
    // fused reshape epilogue: (bt, 3C) -> q/k/v (b,h,t,e)
    int colbase = col0 + tc * 4;
    int which = colbase >> 8;            // uniform per thread
    float* dstArr = (which == 0) ? g_q : (which == 1) ? g_k : g_v;
    #pragma unroll
    for (int u = 0; u < 4; u++) {
        int row = row0 + tr * 4 + u;
        int b = row >> 9, t = row & 511;
        #pragma unroll
        for (int v = 0; v < 4; v++) {
            int col = colbase + v;
            int c0 = col & 255;
            int h = c0 >> 5, e = c0 & 31;
            dstArr[(((b * Hh + h) * Tt) + t) * Ee + e] = acc[u][v];
        }
    }
}

// plain output GEMM: out = g_y @ w_proj
__global__ void __launch_bounds__(256) gemm_out(const float* __restrict__ A,
                                                const float* __restrict__ Bm,
                                                float* __restrict__ Cm) {
    __shared__ float As[64][17];
    __shared__ float Bs[16][68];
    const int tid = threadIdx.x;
    const int tr = tid >> 4, tc = tid & 15;
    const int row0 = blockIdx.y * 64;
    const int col0 = blockIdx.x * 64;
    float acc[4][4] = {};
    for (int k0 = 0; k0 < Cc; k0 += 16) {
        #pragma unroll
        for (int x = tid; x < 1024; x += 256) {
            int r = x >> 4, c = x & 15;
            As[r][c] = A[(row0 + r) * Cc + k0 + c];
        }
        #pragma unroll
        for (int x = tid; x < 1024; x += 256) {
            int r = x >> 6, c = x & 63;
            Bs[r][c] = Bm[(k0 + r) * Cc + col0 + c];
        }
        __syncthreads();
        #pragma unroll
        for (int kk = 0; kk < 16; kk++) {
            float a[4], bv[4];
            #pragma unroll
            for (int u = 0; u < 4; u++) a[u] = As[tr * 4 + u][kk];
            #pragma unroll
            for (int v = 0; v < 4; v++) bv[v] = Bs[kk][tc * 4 + v];
            #pragma unroll
            for (int u = 0; u < 4; u++)
                #pragma unroll
                for (int v = 0; v < 4; v++) acc[u][v] += a[u] * bv[v];
        }
        __syncthreads();
    }
    #pragma unroll
    for (int u = 0; u < 4; u++)
        #pragma unroll
        for (int v = 0; v < 4; v++)
            Cm[(row0 + tr * 4 + u) * Cc + col0 + tc * 4 + v] = acc[u][v];
}

// ---------------- edge-type tables: ekt/evt [h][t16][e] ----------------
__global__ void edge_tables(const float* __restrict__ eet,
                            const float* __restrict__ wek,
                            const float* __restrict__ wev) {
    int idx = blockIdx.x * blockDim.x + threadIdx.x;
    if (idx >= NET * Cc) return;
    int t = idx / Cc, c0 = idx % Cc;
    int h = c0 >> 5, e = c0 & 31;
    float sk = 0.f, sv = 0.f;
    for (int c = 0; c < Cc; c++) {
        float a = eet[t * Cc + c];
        sk += a * wek[c * Cc + c0];
        sv += a * wev[c * Cc + c0];
    }
    g_ekt[(h * NET + t) * Ee + e] = sk;
    g_evt[(h * NET + t) * Ee + e] = sv;
}

// ---------------- fused causal attention with edge modulation ----------------
// grid: (T/8, H, B), block 256 (8 warps). One warp per query row.
// 64-wide j tiles. Phase1: lane=j (two 32-halves, float4 swizzled LDS).
// Phase2: lane=e, (p, evt-offset) broadcast from smem, 4 acc chains.
__global__ void __launch_bounds__(256) attn_kernel(const int* __restrict__ bm,
                                                   const float* __restrict__ abt) {
    const int b = blockIdx.z, h = blockIdx.y;
    const int tid = threadIdx.x;
    const int w = tid >> 5, lane = tid & 31;
    const int it = gridDim.x - 1 - blockIdx.x;   // heavy tiles first
    const int i = it * 8 + w;
    const int i0 = it * 8;

    __shared__ float4 ks4[64 * 8];        // swizzled: (jj, c4) at jj*8 + (c4^(jj&7))
    __shared__ float  v_s[64 * 33];       // pad-33 scalar
    __shared__ float4 qek4[8 * 16 * 8];   // per-warp, swizzled like ks4 keyed on type
    __shared__ float  evt_s[NET * 33];
    __shared__ float2 pe_s[8 * 64];       // per-warp (p, evt byte-offset as float bits)
    __shared__ int    et_s[64 * 9];       // [jj][w] pad-9
    __shared__ float  bias_s[NET];

    const float* qb = g_q + (size_t)(b * Hh + h) * Tt * Ee;
    const float* kb = g_k + (size_t)(b * Hh + h) * Tt * Ee;
    const float* vb = g_v + (size_t)(b * Hh + h) * Tt * Ee;
    const int* bm_b = bm + (size_t)b * Tt * Tt;

    for (int x = tid; x < NET * Ee; x += 256)
        evt_s[(x >> 5) * 33 + (x & 31)] = g_evt[h * NET * Ee + x];
    if (tid < NET) bias_s[tid] = abt[tid * Hh + h];

    {   // per-warp modulated q rows: qek[type][e] = q[i][e] * ekt[type][e]
        float qv = qb[i * Ee + lane];
        float* qf = (float*)qek4;
        #pragma unroll
        for (int t = 0; t < NET; t++) {
            float val = qv * g_ekt[(h * NET + t) * Ee + lane];
            qf[w * 512 + t * 32 + (((lane >> 2) ^ (t & 7)) << 2) + (lane & 3)] = val;
        }
    }
    __syncthreads();

    float m = -INFINITY, l = 0.f;
    float acc0 = 0.f, acc1 = 0.f, acc2 = 0.f, acc3 = 0.f;
    const float inv_scale = 0.1767766952966369f;   // 1/sqrt(32)
    const int ntiles = (it >> 3) + 1;

    for (int tile = 0; tile < ntiles; tile++) {
        const int j0 = tile * 64;
        // cooperative loads: k (swizzled f4), v (pad33), bm-transpose tile
        for (int x = tid; x < 512; x += 256) {
            int jj = x >> 3, c4 = x & 7;
            float4 kv = ((const float4*)kb)[(j0 + jj) * 8 + c4];
            ks4[jj * 8 + (c4 ^ (jj & 7))] = kv;
            float4 vv = ((const float4*)vb)[(j0 + jj) * 8 + c4];
            float* vd = &v_s[jj * 33 + c4 * 4];
            vd[0] = vv.x; vd[1] = vv.y; vd[2] = vv.z; vd[3] = vv.w;
        }
        for (int x = tid; x < 512; x += 256) {
            int jj = x >> 3, iw = x & 7;
            et_s[jj * 9 + iw] = bm_b[(j0 + jj) * Tt + i0 + iw];
        }
        __syncthreads();

        float s0 = -INFINITY, s1 = -INFINITY;
        int et0 = 0, et1 = 0;
        {   // half 0: j = j0 + lane
            int jg = j0 + lane;
            et0 = et_s[lane * 9 + w];
            const float4* qrow = qek4 + w * 128 + et0 * 8;
            const float4* krow = ks4 + lane * 8;
            int qx = et0 & 7, kx = lane & 7;
            float4 a = {0.f, 0.f, 0.f, 0.f};
            #pragma unroll
            for (int c = 0; c < 8; c++) {
                float4 qv4 = qrow[c ^ qx];
                float4 kv4 = krow[c ^ kx];
                a.x += qv4.x * kv4.x; a.y += qv4.y * kv4.y;
                a.z += qv4.z * kv4.z; a.w += qv4.w * kv4.w;
            }
            float s = (a.x + a.y) + (a.z + a.w);
            int et2 = bm_b[i * Tt + jg];
            s = s * inv_scale + bias_s[et2];
            s0 = (jg <= i) ? s : -INFINITY;
        }
        if (j0 + 32 <= i) {   // half 1 (uniform skip when fully masked)
            int jg = j0 + 32 + lane;
            et1 = et_s[(32 + lane) * 9 + w];
            const float4* qrow = qek4 + w * 128 + et1 * 8;
            const float4* krow = ks4 + (32 + lane) * 8;
            int qx = et1 & 7, kx = lane & 7;
            float4 a = {0.f, 0.f, 0.f, 0.f};
            #pragma unroll
            for (int c = 0; c < 8; c++) {
                float4 qv4 = qrow[c ^ qx];
                float4 kv4 = krow[c ^ kx];
                a.x += qv4.x * kv4.x; a.y += qv4.y * kv4.y;
                a.z += qv4.z * kv4.z; a.w += qv4.w * kv4.w;
            }
            float s = (a.x + a.y) + (a.z + a.w);
            int et2 = bm_b[i * Tt + jg];
            s = s * inv_scale + bias_s[et2];
            s1 = (jg <= i) ? s : -INFINITY;
        }

        // ---- online softmax over the 64-wide tile
        float tmax = fmaxf(s0, s1);
        #pragma unroll
        for (int o = 16; o; o >>= 1)
            tmax = fmaxf(tmax, __shfl_xor_sync(0xffffffffu, tmax, o));
        float m_new = fmaxf(m, tmax);          // finite: every tile has >=1 valid j
        float p0 = __expf(s0 - m_new);         // exp(-inf)=0 handles masked lanes
        float p1 = __expf(s1 - m_new);
        float psum = p0 + p1;
        #pragma unroll
        for (int o = 16; o; o >>= 1)
            psum += __shfl_xor_sync(0xffffffffu, psum, o);
        float corr = __expf(m - m_new);
        l = l * corr + psum;
        m = m_new;
        acc0 *= corr; acc1 *= corr; acc2 *= corr; acc3 *= corr;

        pe_s[w * 64 + lane]      = make_float2(p0, __int_as_float(et0 * 132));
        pe_s[w * 64 + 32 + lane] = make_float2(p1, __int_as_float(et1 * 132));
        __syncwarp();

        // ---- phase 2: lane = e. acc[e] += p_j * v[j][e] * evt[et_j][e]
        int jlim = i - j0 + 1;
        if (jlim > 64) jlim = 64;
        int jlim8 = (jlim + 7) & ~7;           // pe entries beyond jlim have p=0
        const float* vrow = v_s + lane;
        const char* evt_base = (const char*)evt_s + lane * 4;
        const float2* per = pe_s + w * 64;
        for (int j8 = 0; j8 < jlim8; j8 += 8) {
            #pragma unroll
            for (int u = 0; u < 8; u++) {
                float2 pe = per[j8 + u];
                float ev = *(const float*)(evt_base + __float_as_int(pe.y));
                float vv = vrow[(j8 + u) * 33];
                float t = pe.x * vv;
                if ((u & 3) == 0) acc0 += t * ev;
                else if ((u & 3) == 1) acc1 += t * ev;
                else if ((u & 3) == 2) acc2 += t * ev;
                else acc3 += t * ev;
            }
        }
        __syncthreads();
    }
    float out = ((acc0 + acc1) + (acc2 + acc3)) / l;
    g_y[(size_t)(b * Tt + i) * Cc + h * Ee + lane] = out;
}

// ---------------- launch ----------------
extern "C" void kernel_launch(void* const* d_in, const int* in_sizes, int n_in,
                              void* d_out, int out_size) {
    const float* x      = (const float*)d_in[0];
    const int*   bm     = (const int*)d_in[1];
    const float* w_attn = (const float*)d_in[2];
    const float* w_proj = (const float*)d_in[3];
    const float* w_ek   = (const float*)d_in[4];
    const float* w_ev   = (const float*)d_in[5];
    const float* eet    = (const float*)d_in[6];
    const float* abt    = (const float*)d_in[7];
    float* out = (float*)d_out;

    float* gy; cudaGetSymbolAddress((void**)&gy, g_y);

    // edge tables first (independent, tiny)
    edge_tables<<<(NET * Cc + 255) / 256, 256>>>(eet, w_ek, w_ev);
    // qkv = x @ w_attn with fused (b,h,t,e) reshape epilogue
    gemm_qkv<<<dim3(C3 / 64, BT / 64), 256>>>(x, w_attn);
    // fused attention -> g_y (b,t,c)
    attn_kernel<<<dim3(Tt / 8, Hh, Bb), 256>>>(bm, abt);
    // out = y @ w_proj
    gemm_out<<<dim3(Cc / 64, BT / 64), 256>>>(gy, w_proj, out);
}

// round 3
// speedup vs baseline: 1.4847x; 1.1424x over previous
#include <cuda_runtime.h>
#include <math.h>

#define Bb 2
#define Tt 512
#define Cc 256
#define Hh 8
#define Ee 32
#define NET 16
#define BT (Bb*Tt)      // 1024
#define C3 (3*Cc)       // 768

// ------- scratch (device globals: no allocation allowed) -------
__device__ float g_q[Bb*Hh*Tt*Ee];    // (b,h,t,e)
__device__ float g_k[Bb*Hh*Tt*Ee];
__device__ float g_v[Bb*Hh*Tt*Ee];
__device__ float g_ekt[Hh*NET*Ee];    // [h][type][e]
__device__ float g_evt[Hh*NET*Ee];
__device__ float g_y[BT*Cc];          // (b,t,c) pre-proj

// ---------------- 32x64 fp32 GEMM: qkv with fused reshape ----------------
__global__ void __launch_bounds__(256) gemm_qkv(const float* __restrict__ A,
                                                const float* __restrict__ Bm) {
    __shared__ float As[32][17];
    __shared__ float Bs[16][68];
    const int tid = threadIdx.x;
    const int tr = tid >> 4, tc = tid & 15;
    const int row0 = blockIdx.y * 32;
    const int col0 = blockIdx.x * 64;
    float acc[2][4] = {};
    for (int k0 = 0; k0 < Cc; k0 += 16) {
        #pragma unroll
        for (int x = tid; x < 512; x += 256) {
            int r = x >> 4, c = x & 15;
            As[r][c] = A[(row0 + r) * Cc + k0 + c];
        }
        #pragma unroll
        for (int x = tid; x < 1024; x += 256) {
            int r = x >> 6, c = x & 63;
            Bs[r][c] = Bm[(k0 + r) * C3 + col0 + c];
        }
        __syncthreads();
        #pragma unroll
        for (int kk = 0; kk < 16; kk++) {
            float a0 = As[tr * 2 + 0][kk];
            float a1 = As[tr * 2 + 1][kk];
            float4 b4 = *(const float4*)&Bs[kk][tc * 4];
            acc[0][0] += a0 * b4.x; acc[0][1] += a0 * b4.y;
            acc[0][2] += a0 * b4.z; acc[0][3] += a0 * b4.w;
            acc[1][0] += a1 * b4.x; acc[1][1] += a1 * b4.y;
            acc[1][2] += a1 * b4.z; acc[1][3] += a1 * b4.w;
        }
        __syncthreads();
    }
    // fused reshape epilogue: (bt, 3C) -> q/k/v (b,h,t,e)
    int colbase = col0 + tc * 4;
    int which = colbase >> 8;            // uniform (64 | 256)
    float* dstArr = (which == 0) ? g_q : (which == 1) ? g_k : g_v;
    #pragma unroll
    for (int u = 0; u < 2; u++) {
        int row = row0 + tr * 2 + u;
        int b = row >> 9, t = row & 511;
        #pragma unroll
        for (int v = 0; v < 4; v++) {
            int c0 = (colbase + v) & 255;
            int h = c0 >> 5, e = c0 & 31;
            dstArr[(((b * Hh + h) * Tt) + t) * Ee + e] = acc[u][v];
        }
    }
}

// ---------------- 32x64 fp32 GEMM: out = g_y @ w_proj ----------------
__global__ void __launch_bounds__(256) gemm_out(const float* __restrict__ A,
                                                const float* __restrict__ Bm,
                                                float* __restrict__ Cm) {
    __shared__ float As[32][17];
    __shared__ float Bs[16][68];
    const int tid = threadIdx.x;
    const int tr = tid >> 4, tc = tid & 15;
    const int row0 = blockIdx.y * 32;
    const int col0 = blockIdx.x * 64;
    float acc[2][4] = {};
    for (int k0 = 0; k0 < Cc; k0 += 16) {
        #pragma unroll
        for (int x = tid; x < 512; x += 256) {
            int r = x >> 4, c = x & 15;
            As[r][c] = A[(row0 + r) * Cc + k0 + c];
        }
        #pragma unroll
        for (int x = tid; x < 1024; x += 256) {
            int r = x >> 6, c = x & 63;
            Bs[r][c] = Bm[(k0 + r) * Cc + col0 + c];
        }
        __syncthreads();
        #pragma unroll
        for (int kk = 0; kk < 16; kk++) {
            float a0 = As[tr * 2 + 0][kk];
            float a1 = As[tr * 2 + 1][kk];
            float4 b4 = *(const float4*)&Bs[kk][tc * 4];
            acc[0][0] += a0 * b4.x; acc[0][1] += a0 * b4.y;
            acc[0][2] += a0 * b4.z; acc[0][3] += a0 * b4.w;
            acc[1][0] += a1 * b4.x; acc[1][1] += a1 * b4.y;
            acc[1][2] += a1 * b4.z; acc[1][3] += a1 * b4.w;
        }
        __syncthreads();
    }
    #pragma unroll
    for (int u = 0; u < 2; u++)
        #pragma unroll
        for (int v = 0; v < 4; v++)
            Cm[(row0 + tr * 2 + u) * Cc + col0 + tc * 4 + v] = acc[u][v];
}

// ---------------- edge-type tables: ekt/evt [h][t16][e] ----------------
__global__ void edge_tables(const float* __restrict__ eet,
                            const float* __restrict__ wek,
                            const float* __restrict__ wev) {
    int idx = blockIdx.x * blockDim.x + threadIdx.x;
    if (idx >= NET * Cc) return;
    int t = idx / Cc, c0 = idx % Cc;
    int h = c0 >> 5, e = c0 & 31;
    float sk = 0.f, sv = 0.f;
    for (int c = 0; c < Cc; c++) {
        float a = eet[t * Cc + c];
        sk += a * wek[c * Cc + c0];
        sv += a * wev[c * Cc + c0];
    }
    g_ekt[(h * NET + t) * Ee + e] = sk;
    g_evt[(h * NET + t) * Ee + e] = sv;
}

// ---------------- fused causal attention: 2 query rows per warp ----------------
// grid (T/16, H, B), 256 threads (8 warps). Warp w -> rows i0+w, i0+w+8.
// dynamic smem partition (bytes):
#define OFF_KS4   0                    // float4[64*8]        8192
#define OFF_VS    8192                 // float [64*33]       8448
#define OFF_QEK   16640                // float4[8*2*16*8]    32768
#define OFF_EVT   49408                // float [16*33]       2112
#define OFF_PE    51520                // float2[8*2*64]      8192
#define OFF_ET    59712                // int   [64*17]       4352
#define OFF_EB    64064                // int   [16*65]       4160
#define OFF_BIAS  68224                // float [16]          64
#define SMEM_ATTN 68288

__global__ void __launch_bounds__(256) attn_kernel(const int* __restrict__ bm,
                                                   const float* __restrict__ abt) {
    extern __shared__ char sm[];
    float4* ks4   = (float4*)(sm + OFF_KS4);
    float*  v_s   = (float*) (sm + OFF_VS);
    float4* qek4  = (float4*)(sm + OFF_QEK);
    float*  qekf  = (float*) (sm + OFF_QEK);
    float*  evt_s = (float*) (sm + OFF_EVT);
    float2* pe_s  = (float2*)(sm + OFF_PE);
    int*    et_s  = (int*)   (sm + OFF_ET);
    int*    eb_s  = (int*)   (sm + OFF_EB);
    float*  bias_s= (float*) (sm + OFF_BIAS);

    const int b = blockIdx.z, h = blockIdx.y;
    const int tid = threadIdx.x;
    const int w = tid >> 5, lane = tid & 31;
    const int itile = gridDim.x - 1 - blockIdx.x;   // heavy tiles first
    const int i0 = itile * 16;
    const int iA = i0 + w;
    const int iB = i0 + w + 8;

    const float* qb = g_q + (size_t)(b * Hh + h) * Tt * Ee;
    const float4* kb4 = (const float4*)(g_k + (size_t)(b * Hh + h) * Tt * Ee);
    const float4* vb4 = (const float4*)(g_v + (size_t)(b * Hh + h) * Tt * Ee);
    const int* bm_b = bm + (size_t)b * Tt * Tt;

    for (int x = tid; x < NET * Ee; x += 256)
        evt_s[(x >> 5) * 33 + (x & 31)] = g_evt[h * NET * Ee + x];
    if (tid < NET) bias_s[tid] = abt[tid * Hh + h];

    {   // per-warp modulated q tables for both rows
        float qA = qb[iA * Ee + lane];
        float qB = qb[iB * Ee + lane];
        int swzbase = ((lane >> 2)) ;
        #pragma unroll
        for (int t = 0; t < NET; t++) {
            float ek = g_ekt[(h * NET + t) * Ee + lane];
            int swz = ((swzbase ^ (t & 7)) << 2) | (lane & 3);
            qekf[((w * 2 + 0) * 16 + t) * 32 + swz] = qA * ek;
            qekf[((w * 2 + 1) * 16 + t) * 32 + swz] = qB * ek;
        }
    }
    __syncthreads();

    float mA = -INFINITY, lA = 0.f, mB = -INFINITY, lB = 0.f;
    float accA[4] = {}, accB[4] = {};
    const float inv_scale = 0.1767766952966369f;   // 1/sqrt(32)
    const int ntiles = ((i0 + 15) >> 6) + 1;

    for (int tile = 0; tile < ntiles; tile++) {
        const int j0 = tile * 64;
        // cooperative loads
        #pragma unroll
        for (int x = tid; x < 512; x += 256) {
            int jj = x >> 3, c4 = x & 7;
            ks4[jj * 8 + (c4 ^ (jj & 7))] = kb4[(j0 + jj) * 8 + c4];
            float4 vv = vb4[(j0 + jj) * 8 + c4];
            float* vd = &v_s[jj * 33 + c4 * 4];
            vd[0] = vv.x; vd[1] = vv.y; vd[2] = vv.z; vd[3] = vv.w;
        }
        #pragma unroll
        for (int x = tid; x < 1024; x += 256) {
            int jj = x >> 4, iw = x & 15;
            et_s[jj * 17 + iw] = bm_b[(j0 + jj) * Tt + i0 + iw];
        }
        #pragma unroll
        for (int x = tid; x < 1024; x += 256) {
            int iw = x >> 6, jj = x & 63;
            eb_s[iw * 65 + jj] = bm_b[(i0 + iw) * Tt + j0 + jj];
        }
        __syncthreads();

        if (j0 <= iB) {
            const float4* krow = ks4 + lane * 8;
            const int kx = lane & 7;
            float sA0, sB0, sA1 = -INFINITY, sB1 = -INFINITY;
            int etA0, etB0, etA1 = 0, etB1 = 0;
            float pA1 = 0.f, pB1 = 0.f;

            {   // half 0: j = j0 + lane
                int jg = j0 + lane;
                etA0 = et_s[lane * 17 + w];
                etB0 = et_s[lane * 17 + w + 8];
                const float4* qrA = qek4 + ((w * 2 + 0) * 16 + etA0) * 8;
                const float4* qrB = qek4 + ((w * 2 + 1) * 16 + etB0) * 8;
                int qxA = etA0 & 7, qxB = etB0 & 7;
                float4 aA = {0,0,0,0}, aB = {0,0,0,0};
                #pragma unroll
                for (int c = 0; c < 8; c++) {
                    float4 k4 = krow[c ^ kx];
                    float4 qa = qrA[c ^ qxA];
                    float4 qc = qrB[c ^ qxB];
                    aA.x += qa.x * k4.x; aA.y += qa.y * k4.y;
                    aA.z += qa.z * k4.z; aA.w += qa.w * k4.w;
                    aB.x += qc.x * k4.x; aB.y += qc.y * k4.y;
                    aB.z += qc.z * k4.z; aB.w += qc.w * k4.w;
                }
                float dA = (aA.x + aA.y) + (aA.z + aA.w);
                float dB = (aB.x + aB.y) + (aB.z + aB.w);
                float bA = bias_s[eb_s[w * 65 + lane]];
                float bB = bias_s[eb_s[(w + 8) * 65 + lane]];
                sA0 = (jg <= iA) ? dA * inv_scale + bA : -INFINITY;
                sB0 = (jg <= iB) ? dB * inv_scale + bB : -INFINITY;
            }
            const bool h1 = (j0 + 32 <= iB);
            if (h1) {   // half 1: j = j0 + 32 + lane
                int jg = j0 + 32 + lane;
                etA1 = et_s[(32 + lane) * 17 + w];
                etB1 = et_s[(32 + lane) * 17 + w + 8];
                const float4* kr2 = ks4 + (32 + lane) * 8;
                int kx2 = (lane + 32) & 7;  // == kx
                const float4* qrA = qek4 + ((w * 2 + 0) * 16 + etA1) * 8;
                const float4* qrB = qek4 + ((w * 2 + 1) * 16 + etB1) * 8;
                int qxA = etA1 & 7, qxB = etB1 & 7;
                float4 aA = {0,0,0,0}, aB = {0,0,0,0};
                #pragma unroll
                for (int c = 0; c < 8; c++) {
                    float4 k4 = kr2[c ^ kx2];
                    float4 qa = qrA[c ^ qxA];
                    float4 qc = qrB[c ^ qxB];
                    aA.x += qa.x * k4.x; aA.y += qa.y * k4.y;
                    aA.z += qa.z * k4.z; aA.w += qa.w * k4.w;
                    aB.x += qc.x * k4.x; aB.y += qc.y * k4.y;
                    aB.z += qc.z * k4.z; aB.w += qc.w * k4.w;
                }
                float dA = (aA.x + aA.y) + (aA.z + aA.w);
                float dB = (aB.x + aB.y) + (aB.z + aB.w);
                float bA = bias_s[eb_s[w * 65 + 32 + lane]];
                float bB = bias_s[eb_s[(w + 8) * 65 + 32 + lane]];
                sA1 = (jg <= iA) ? dA * inv_scale + bA : -INFINITY;
                sB1 = (jg <= iB) ? dB * inv_scale + bB : -INFINITY;
            }

            // online softmax, rows A and B
            float tA = fmaxf(sA0, sA1), tB = fmaxf(sB0, sB1);
            #pragma unroll
            for (int o = 16; o; o >>= 1) {
                tA = fmaxf(tA, __shfl_xor_sync(0xffffffffu, tA, o));
                tB = fmaxf(tB, __shfl_xor_sync(0xffffffffu, tB, o));
            }
            float mnA = fmaxf(mA, tA), mnB = fmaxf(mB, tB);
            float pA0 = __expf(sA0 - mnA), pB0 = __expf(sB0 - mnB);
            if (h1) { pA1 = __expf(sA1 - mnA); pB1 = __expf(sB1 - mnB); }
            float psA = pA0 + pA1, psB = pB0 + pB1;
            #pragma unroll
            for (int o = 16; o; o >>= 1) {
                psA += __shfl_xor_sync(0xffffffffu, psA, o);
                psB += __shfl_xor_sync(0xffffffffu, psB, o);
            }
            float cA = __expf(mA - mnA), cB = __expf(mB - mnB);
            lA = lA * cA + psA; lB = lB * cB + psB;
            mA = mnA; mB = mnB;
            #pragma unroll
            for (int u = 0; u < 4; u++) { accA[u] *= cA; accB[u] *= cB; }

            float2* pa = pe_s + (w * 2 + 0) * 64;
            float2* pb = pe_s + (w * 2 + 1) * 64;
            pa[lane] = make_float2(pA0, __int_as_float(etA0 * 132));
            pb[lane] = make_float2(pB0, __int_as_float(etB0 * 132));
            if (h1) {
                pa[32 + lane] = make_float2(pA1, __int_as_float(etA1 * 132));
                pb[32 + lane] = make_float2(pB1, __int_as_float(etB1 * 132));
            }
            __syncwarp();

            // phase 2: lane = e
            int jlim = iB - j0 + 1; if (jlim > 64) jlim = 64;
            int jlim8 = (jlim + 7) & ~7;
            const float* vrow = v_s + lane;
            const char* evb = (const char*)evt_s + lane * 4;
            for (int j8 = 0; j8 < jlim8; j8 += 8) {
                #pragma unroll
                for (int u = 0; u < 8; u++) {
                    float2 eA = pa[j8 + u];
                    float2 eB = pb[j8 + u];
                    float vv = vrow[(j8 + u) * 33];
                    float evA = *(const float*)(evb + __float_as_int(eA.y));
                    float evB = *(const float*)(evb + __float_as_int(eB.y));
                    accA[u & 3] += (eA.x * vv) * evA;
                    accB[u & 3] += (eB.x * vv) * evB;
                }
            }
        }
        __syncthreads();
    }
    float oA = ((accA[0] + accA[1]) + (accA[2] + accA[3])) / lA;
    float oB = ((accB[0] + accB[1]) + (accB[2] + accB[3])) / lB;
    g_y[(size_t)(b * Tt + iA) * Cc + h * Ee + lane] = oA;
    g_y[(size_t)(b * Tt + iB) * Cc + h * Ee + lane] = oB;
}

// ---------------- launch ----------------
extern "C" void kernel_launch(void* const* d_in, const int* in_sizes, int n_in,
                              void* d_out, int out_size) {
    const float* x      = (const float*)d_in[0];
    const int*   bm     = (const int*)d_in[1];
    const float* w_attn = (const float*)d_in[2];
    const float* w_proj = (const float*)d_in[3];
    const float* w_ek   = (const float*)d_in[4];
    const float* w_ev   = (const float*)d_in[5];
    const float* eet    = (const float*)d_in[6];
    const float* abt    = (const float*)d_in[7];
    float* out = (float*)d_out;

    float* gy; cudaGetSymbolAddress((void**)&gy, g_y);

    cudaFuncSetAttribute(attn_kernel, cudaFuncAttributeMaxDynamicSharedMemorySize, SMEM_ATTN);

    edge_tables<<<(NET * Cc + 255) / 256, 256>>>(eet, w_ek, w_ev);
    gemm_qkv<<<dim3(C3 / 64, BT / 32), 256>>>(x, w_attn);
    attn_kernel<<<dim3(Tt / 16, Hh, Bb), 256, SMEM_ATTN>>>(bm, abt);
    gemm_out<<<dim3(Cc / 64, BT / 32), 256>>>(gy, w_proj, out);
}

// round 4
// speedup vs baseline: 1.8764x; 1.2638x over previous
#include <cuda_runtime.h>
#include <math.h>

#define Bb 2
#define Tt 512
#define Cc 256
#define Hh 8
#define Ee 32
#define NET 16
#define BT (Bb*Tt)      // 1024
#define C3 (3*Cc)       // 768

// ------- scratch (device globals: no allocation allowed) -------
__device__ float g_q[Bb*Hh*Tt*Ee];    // (b,h,t,e)
__device__ float g_k[Bb*Hh*Tt*Ee];
__device__ float g_v[Bb*Hh*Tt*Ee];
__device__ float g_ekt[Hh*NET*Ee];    // [h][type][e]
__device__ float g_evt[Hh*NET*Ee];
__device__ float g_y[BT*Cc];          // (b,t,c) pre-proj

// =====================================================================
// 32x64 fp32 GEMM, TK=32, double-buffered smem + register prefetch.
// One __syncthreads per k-iteration. 256 threads, 2x4 micro-tile.
// =====================================================================

// ---- qkv variant (N=768) with fused reshape epilogue + edge-table blocks ----
__global__ void __launch_bounds__(256) gemm_qkv(const float* __restrict__ A,
                                                const float* __restrict__ Bm,
                                                const float* __restrict__ eet,
                                                const float* __restrict__ wek,
                                                const float* __restrict__ wev) {
    const int tid = threadIdx.x;

    if (blockIdx.x == 12) {
        // edge-table blocks: ekt/evt [h][type][e]
        if (blockIdx.y < 16) {
            int idx = blockIdx.y * 256 + tid;       // 0..4095 = NET*Cc
            int t = idx >> 8, c0 = idx & 255;
            int h = c0 >> 5, e = c0 & 31;
            float sk = 0.f, sv = 0.f;
            #pragma unroll 4
            for (int c = 0; c < Cc; c++) {
                float a = eet[t * Cc + c];
                sk += a * wek[c * Cc + c0];
                sv += a * wev[c * Cc + c0];
            }
            g_ekt[(h * NET + t) * Ee + e] = sk;
            g_evt[(h * NET + t) * Ee + e] = sv;
        }
        return;
    }

    __shared__ float As[2][32][40];
    __shared__ float Bs[2][32][72];
    const int row0 = blockIdx.y * 32;
    const int col0 = blockIdx.x * 64;
    const int ar = tid >> 3, ac = (tid & 7) * 4;    // A tile: 32x32 via float4
    const int br = tid >> 4, bc = (tid & 15) * 4;   // B tile: 32x64, 2 f4/thread
    const int tr = tid >> 4, tc = tid & 15;

    float4 arg, brg0, brg1;
    // prologue: tile 0
    arg  = *(const float4*)&A[(row0 + ar) * Cc + ac];
    brg0 = *(const float4*)&Bm[br * C3 + col0 + bc];
    brg1 = *(const float4*)&Bm[(br + 16) * C3 + col0 + bc];
    *(float4*)&As[0][ar][ac] = arg;
    *(float4*)&Bs[0][br][bc] = brg0;
    *(float4*)&Bs[0][br + 16][bc] = brg1;
    __syncthreads();

    float acc[2][4] = {};
    #pragma unroll 1
    for (int it = 0; it < 8; it++) {
        const int buf = it & 1;
        if (it < 7) {
            int k0 = (it + 1) * 32;
            arg  = *(const float4*)&A[(row0 + ar) * Cc + k0 + ac];
            brg0 = *(const float4*)&Bm[(k0 + br) * C3 + col0 + bc];
            brg1 = *(const float4*)&Bm[(k0 + br + 16) * C3 + col0 + bc];
        }
        #pragma unroll
        for (int kk = 0; kk < 32; kk++) {
            float a0 = As[buf][tr * 2 + 0][kk];
            float a1 = As[buf][tr * 2 + 1][kk];
            float4 b4 = *(const float4*)&Bs[buf][kk][tc * 4];
            acc[0][0] += a0 * b4.x; acc[0][1] += a0 * b4.y;
            acc[0][2] += a0 * b4.z; acc[0][3] += a0 * b4.w;
            acc[1][0] += a1 * b4.x; acc[1][1] += a1 * b4.y;
            acc[1][2] += a1 * b4.z; acc[1][3] += a1 * b4.w;
        }
        if (it < 7) {
            const int nb = buf ^ 1;
            *(float4*)&As[nb][ar][ac] = arg;
            *(float4*)&Bs[nb][br][bc] = brg0;
            *(float4*)&Bs[nb][br + 16][bc] = brg1;
            __syncthreads();
        }
    }
    // fused reshape epilogue: (bt, 3C) -> q/k/v (b,h,t,e)
    int colbase = col0 + tc * 4;
    int which = colbase >> 8;
    float* dstArr = (which == 0) ? g_q : (which == 1) ? g_k : g_v;
    #pragma unroll
    for (int u = 0; u < 2; u++) {
        int row = row0 + tr * 2 + u;
        int b = row >> 9, t = row & 511;
        int h = (colbase & 255) >> 5;   // 4 consecutive cols share h (colbase%4==0)
        int e = colbase & 31;
        *(float4*)&dstArr[(((b * Hh + h) * Tt) + t) * Ee + e] =
            make_float4(acc[u][0], acc[u][1], acc[u][2], acc[u][3]);
    }
}

// ---- out variant (N=256) ----
__global__ void __launch_bounds__(256) gemm_out(const float* __restrict__ A,
                                                const float* __restrict__ Bm,
                                                float* __restrict__ Cm) {
    __shared__ float As[2][32][40];
    __shared__ float Bs[2][32][72];
    const int tid = threadIdx.x;
    const int row0 = blockIdx.y * 32;
    const int col0 = blockIdx.x * 64;
    const int ar = tid >> 3, ac = (tid & 7) * 4;
    const int br = tid >> 4, bc = (tid & 15) * 4;
    const int tr = tid >> 4, tc = tid & 15;

    float4 arg, brg0, brg1;
    arg  = *(const float4*)&A[(row0 + ar) * Cc + ac];
    brg0 = *(const float4*)&Bm[br * Cc + col0 + bc];
    brg1 = *(const float4*)&Bm[(br + 16) * Cc + col0 + bc];
    *(float4*)&As[0][ar][ac] = arg;
    *(float4*)&Bs[0][br][bc] = brg0;
    *(float4*)&Bs[0][br + 16][bc] = brg1;
    __syncthreads();

    float acc[2][4] = {};
    #pragma unroll 1
    for (int it = 0; it < 8; it++) {
        const int buf = it & 1;
        if (it < 7) {
            int k0 = (it + 1) * 32;
            arg  = *(const float4*)&A[(row0 + ar) * Cc + k0 + ac];
            brg0 = *(const float4*)&Bm[(k0 + br) * Cc + col0 + bc];
            brg1 = *(const float4*)&Bm[(k0 + br + 16) * Cc + col0 + bc];
        }
        #pragma unroll
        for (int kk = 0; kk < 32; kk++) {
            float a0 = As[buf][tr * 2 + 0][kk];
            float a1 = As[buf][tr * 2 + 1][kk];
            float4 b4 = *(const float4*)&Bs[buf][kk][tc * 4];
            acc[0][0] += a0 * b4.x; acc[0][1] += a0 * b4.y;
            acc[0][2] += a0 * b4.z; acc[0][3] += a0 * b4.w;
            acc[1][0] += a1 * b4.x; acc[1][1] += a1 * b4.y;
            acc[1][2] += a1 * b4.z; acc[1][3] += a1 * b4.w;
        }
        if (it < 7) {
            const int nb = buf ^ 1;
            *(float4*)&As[nb][ar][ac] = arg;
            *(float4*)&Bs[nb][br][bc] = brg0;
            *(float4*)&Bs[nb][br + 16][bc] = brg1;
            __syncthreads();
        }
    }
    #pragma unroll
    for (int u = 0; u < 2; u++)
        *(float4*)&Cm[(row0 + tr * 2 + u) * Cc + col0 + tc * 4] =
            make_float4(acc[u][0], acc[u][1], acc[u][2], acc[u][3]);
}

// ---------------- fused causal attention: 2 query rows per warp ----------------
// grid (T/16, H, B), 256 threads (8 warps). Warp w -> rows i0+w, i0+w+8.
#define OFF_KS4   0                    // float4[64*8]        8192
#define OFF_VS    8192                 // float [64*33]       8448
#define OFF_QEK   16640                // float4[8*2*16*8]    32768
#define OFF_EVT   49408                // float [16*33]       2112
#define OFF_PE    51520                // float4[8*64]        8192
#define OFF_ET    59712                // int   [64*17]       4352
#define OFF_EB    64064                // int   [16*65]       4160
#define OFF_BIAS  68224                // float [16]          64
#define SMEM_ATTN 68288

__global__ void __launch_bounds__(256) attn_kernel(const int* __restrict__ bm,
                                                   const float* __restrict__ abt) {
    extern __shared__ char sm[];
    float4* ks4   = (float4*)(sm + OFF_KS4);
    float*  v_s   = (float*) (sm + OFF_VS);
    float4* qek4  = (float4*)(sm + OFF_QEK);
    float*  qekf  = (float*) (sm + OFF_QEK);
    float*  evt_s = (float*) (sm + OFF_EVT);
    float4* pe_s  = (float4*)(sm + OFF_PE);
    int*    et_s  = (int*)   (sm + OFF_ET);
    int*    eb_s  = (int*)   (sm + OFF_EB);
    float*  bias_s= (float*) (sm + OFF_BIAS);

    const int b = blockIdx.z, h = blockIdx.y;
    const int tid = threadIdx.x;
    const int w = tid >> 5, lane = tid & 31;
    const int itile = gridDim.x - 1 - blockIdx.x;   // heavy tiles first
    const int i0 = itile * 16;
    const int iA = i0 + w;
    const int iB = i0 + w + 8;

    const float* qb = g_q + (size_t)(b * Hh + h) * Tt * Ee;
    const float4* kb4 = (const float4*)(g_k + (size_t)(b * Hh + h) * Tt * Ee);
    const float4* vb4 = (const float4*)(g_v + (size_t)(b * Hh + h) * Tt * Ee);
    const int* bm_b = bm + (size_t)b * Tt * Tt;

    for (int x = tid; x < NET * Ee; x += 256)
        evt_s[(x >> 5) * 33 + (x & 31)] = g_evt[h * NET * Ee + x];
    if (tid < NET) bias_s[tid] = abt[tid * Hh + h];

    {   // per-warp modulated q tables for both rows
        float qA = qb[iA * Ee + lane];
        float qB = qb[iB * Ee + lane];
        int swzbase = lane >> 2;
        #pragma unroll
        for (int t = 0; t < NET; t++) {
            float ek = g_ekt[(h * NET + t) * Ee + lane];
            int swz = ((swzbase ^ (t & 7)) << 2) | (lane & 3);
            qekf[((w * 2 + 0) * 16 + t) * 32 + swz] = qA * ek;
            qekf[((w * 2 + 1) * 16 + t) * 32 + swz] = qB * ek;
        }
    }
    __syncthreads();

    float mA = -INFINITY, lA = 0.f, mB = -INFINITY, lB = 0.f;
    float accA[4] = {}, accB[4] = {};
    const float inv_scale = 0.1767766952966369f;   // 1/sqrt(32)
    const int ntiles = ((i0 + 15) >> 6) + 1;

    for (int tile = 0; tile < ntiles; tile++) {
        const int j0 = tile * 64;
        #pragma unroll
        for (int x = tid; x < 512; x += 256) {
            int jj = x >> 3, c4 = x & 7;
            ks4[jj * 8 + (c4 ^ (jj & 7))] = kb4[(j0 + jj) * 8 + c4];
            float4 vv = vb4[(j0 + jj) * 8 + c4];
            float* vd = &v_s[jj * 33 + c4 * 4];
            vd[0] = vv.x; vd[1] = vv.y; vd[2] = vv.z; vd[3] = vv.w;
        }
        #pragma unroll
        for (int x = tid; x < 1024; x += 256) {
            int jj = x >> 4, iw = x & 15;
            et_s[jj * 17 + iw] = bm_b[(j0 + jj) * Tt + i0 + iw];
        }
        #pragma unroll
        for (int x = tid; x < 1024; x += 256) {
            int iw = x >> 6, jj = x & 63;
            eb_s[iw * 65 + jj] = bm_b[(i0 + iw) * Tt + j0 + jj];
        }
        __syncthreads();

        if (j0 <= iB) {
            const float4* krow = ks4 + lane * 8;
            const int kx = lane & 7;
            float sA0, sB0, sA1 = -INFINITY, sB1 = -INFINITY;
            int etA0, etB0, etA1 = 0, etB1 = 0;
            float pA1 = 0.f, pB1 = 0.f;

            {   // half 0: j = j0 + lane
                int jg = j0 + lane;
                etA0 = et_s[lane * 17 + w];
                etB0 = et_s[lane * 17 + w + 8];
                const float4* qrA = qek4 + ((w * 2 + 0) * 16 + etA0) * 8;
                const float4* qrB = qek4 + ((w * 2 + 1) * 16 + etB0) * 8;
                int qxA = etA0 & 7, qxB = etB0 & 7;
                float4 aA = {0,0,0,0}, aB = {0,0,0,0};
                #pragma unroll
                for (int c = 0; c < 8; c++) {
                    float4 k4 = krow[c ^ kx];
                    float4 qa = qrA[c ^ qxA];
                    float4 qc = qrB[c ^ qxB];
                    aA.x += qa.x * k4.x; aA.y += qa.y * k4.y;
                    aA.z += qa.z * k4.z; aA.w += qa.w * k4.w;
                    aB.x += qc.x * k4.x; aB.y += qc.y * k4.y;
                    aB.z += qc.z * k4.z; aB.w += qc.w * k4.w;
                }
                float dA = (aA.x + aA.y) + (aA.z + aA.w);
                float dB = (aB.x + aB.y) + (aB.z + aB.w);
                float bA = bias_s[eb_s[w * 65 + lane]];
                float bB = bias_s[eb_s[(w + 8) * 65 + lane]];
                sA0 = (jg <= iA) ? dA * inv_scale + bA : -INFINITY;
                sB0 = (jg <= iB) ? dB * inv_scale + bB : -INFINITY;
            }
            const bool h1 = (j0 + 32 <= iB);
            if (h1) {   // half 1: j = j0 + 32 + lane
                int jg = j0 + 32 + lane;
                etA1 = et_s[(32 + lane) * 17 + w];
                etB1 = et_s[(32 + lane) * 17 + w + 8];
                const float4* kr2 = ks4 + (32 + lane) * 8;
                const float4* qrA = qek4 + ((w * 2 + 0) * 16 + etA1) * 8;
                const float4* qrB = qek4 + ((w * 2 + 1) * 16 + etB1) * 8;
                int qxA = etA1 & 7, qxB = etB1 & 7;
                float4 aA = {0,0,0,0}, aB = {0,0,0,0};
                #pragma unroll
                for (int c = 0; c < 8; c++) {
                    float4 k4 = kr2[c ^ kx];
                    float4 qa = qrA[c ^ qxA];
                    float4 qc = qrB[c ^ qxB];
                    aA.x += qa.x * k4.x; aA.y += qa.y * k4.y;
                    aA.z += qa.z * k4.z; aA.w += qa.w * k4.w;
                    aB.x += qc.x * k4.x; aB.y += qc.y * k4.y;
                    aB.z += qc.z * k4.z; aB.w += qc.w * k4.w;
                }
                float dA = (aA.x + aA.y) + (aA.z + aA.w);
                float dB = (aB.x + aB.y) + (aB.z + aB.w);
                float bA = bias_s[eb_s[w * 65 + 32 + lane]];
                float bB = bias_s[eb_s[(w + 8) * 65 + 32 + lane]];
                sA1 = (jg <= iA) ? dA * inv_scale + bA : -INFINITY;
                sB1 = (jg <= iB) ? dB * inv_scale + bB : -INFINITY;
            }

            // online softmax, rows A and B
            float tA = fmaxf(sA0, sA1), tB = fmaxf(sB0, sB1);
            #pragma unroll
            for (int o = 16; o; o >>= 1) {
                tA = fmaxf(tA, __shfl_xor_sync(0xffffffffu, tA, o));
                tB = fmaxf(tB, __shfl_xor_sync(0xffffffffu, tB, o));
            }
            float mnA = fmaxf(mA, tA), mnB = fmaxf(mB, tB);
            float pA0 = __expf(sA0 - mnA), pB0 = __expf(sB0 - mnB);
            if (h1) { pA1 = __expf(sA1 - mnA); pB1 = __expf(sB1 - mnB); }
            float psA = pA0 + pA1, psB = pB0 + pB1;
            #pragma unroll
            for (int o = 16; o; o >>= 1) {
                psA += __shfl_xor_sync(0xffffffffu, psA, o);
                psB += __shfl_xor_sync(0xffffffffu, psB, o);
            }
            float cA = __expf(mA - mnA), cB = __expf(mB - mnB);
            lA = lA * cA + psA; lB = lB * cB + psB;
            mA = mnA; mB = mnB;
            #pragma unroll
            for (int u = 0; u < 4; u++) { accA[u] *= cA; accB[u] *= cB; }

            // packed (pA, offA, pB, offB) per j
            float4* pw = pe_s + w * 64;
            pw[lane] = make_float4(pA0, __int_as_float(etA0 * 132),
                                   pB0, __int_as_float(etB0 * 132));
            if (h1)
                pw[32 + lane] = make_float4(pA1, __int_as_float(etA1 * 132),
                                            pB1, __int_as_float(etB1 * 132));
            __syncwarp();

            // phase 2: lane = e
            int jlim = iB - j0 + 1; if (jlim > 64) jlim = 64;
            int jlim8 = (jlim + 7) & ~7;
            const float* vrow = v_s + lane;
            const char* evb = (const char*)evt_s + lane * 4;
            for (int j8 = 0; j8 < jlim8; j8 += 8) {
                #pragma unroll
                for (int u = 0; u < 8; u++) {
                    float4 pe = pw[j8 + u];
                    float vv = vrow[(j8 + u) * 33];
                    float evA = *(const float*)(evb + __float_as_int(pe.y));
                    float evB = *(const float*)(evb + __float_as_int(pe.w));
                    accA[u & 3] += (pe.x * vv) * evA;
                    accB[u & 3] += (pe.z * vv) * evB;
                }
            }
        }
        __syncthreads();
    }
    float oA = ((accA[0] + accA[1]) + (accA[2] + accA[3])) / lA;
    float oB = ((accB[0] + accB[1]) + (accB[2] + accB[3])) / lB;
    g_y[(size_t)(b * Tt + iA) * Cc + h * Ee + lane] = oA;
    g_y[(size_t)(b * Tt + iB) * Cc + h * Ee + lane] = oB;
}

// ---------------- launch ----------------
extern "C" void kernel_launch(void* const* d_in, const int* in_sizes, int n_in,
                              void* d_out, int out_size) {
    const float* x      = (const float*)d_in[0];
    const int*   bm     = (const int*)d_in[1];
    const float* w_attn = (const float*)d_in[2];
    const float* w_proj = (const float*)d_in[3];
    const float* w_ek   = (const float*)d_in[4];
    const float* w_ev   = (const float*)d_in[5];
    const float* eet    = (const float*)d_in[6];
    const float* abt    = (const float*)d_in[7];
    float* out = (float*)d_out;

    float* gy; cudaGetSymbolAddress((void**)&gy, g_y);

    cudaFuncSetAttribute(attn_kernel, cudaFuncAttributeMaxDynamicSharedMemorySize, SMEM_ATTN);

    // qkv GEMM (+ edge tables in blockIdx.x==12 column)
    gemm_qkv<<<dim3(13, BT / 32), 256>>>(x, w_attn, eet, w_ek, w_ev);
    // fused attention -> g_y (b,t,c)
    attn_kernel<<<dim3(Tt / 16, Hh, Bb), 256, SMEM_ATTN>>>(bm, abt);
    // out = y @ w_proj
    gemm_out<<<dim3(Cc / 64, BT / 32), 256>>>(gy, w_proj, out);
}